// round 7
// baseline (speedup 1.0000x reference)
#include <cuda_runtime.h>
#include <cstdint>

#define NSTEP 2176
#define NPAIR (NSTEP / 2)
#define BURN  128
#define DIMX  512
#define HID   1024
#define GT    16            // t-tile for dz GEMM

// ---------------- scratch (device globals: no allocation allowed) ----------
__device__ float g_dx[NSTEP * DIMX];   // scaled noise: normal * 0.1
__device__ float g_u [NSTEP];          // per-step uniforms
__device__ float g_dz[NSTEP * HID];    // dz[t][j] = sum_i dx[t][i] * W1[i][j]
__device__ float g_z0[HID];            // z0 = x0 @ W1 + b1

// ---------------- threefry2x32 (JAX-exact, partitionable) ------------------
__device__ __forceinline__ uint32_t rotl32(uint32_t v, int r) {
    return (v << r) | (v >> (32 - r));
}
__device__ __forceinline__ void tf2x32(uint32_t k0, uint32_t k1,
                                       uint32_t x0, uint32_t x1,
                                       uint32_t& o0, uint32_t& o1) {
    uint32_t k2 = k0 ^ k1 ^ 0x1BD11BDAu;
    x0 += k0; x1 += k1;
#define TF_R(R) { x0 += x1; x1 = rotl32(x1, R); x1 ^= x0; }
    TF_R(13) TF_R(15) TF_R(26) TF_R(6)
    x0 += k1; x1 += k2 + 1u;
    TF_R(17) TF_R(29) TF_R(16) TF_R(24)
    x0 += k2; x1 += k0 + 2u;
    TF_R(13) TF_R(15) TF_R(26) TF_R(6)
    x0 += k0; x1 += k1 + 3u;
    TF_R(17) TF_R(29) TF_R(16) TF_R(24)
    x0 += k1; x1 += k2 + 4u;
    TF_R(13) TF_R(15) TF_R(26) TF_R(6)
    x0 += k2; x1 += k0 + 5u;
#undef TF_R
    o0 = x0; o1 = x1;
}

__device__ __forceinline__ uint32_t rbits32(uint32_t k0, uint32_t k1, uint32_t idx) {
    uint32_t o0, o1;
    tf2x32(k0, k1, 0u, idx, o0, o1);
    return o0 ^ o1;
}

__device__ __forceinline__ float bits_to_unit(uint32_t b) {
    return __uint_as_float((b >> 9) | 0x3f800000u) - 1.0f;
}

// XLA ErfInv32 (Giles). log1pf == libdevice __nv_log1pf == what XLA emits.
__device__ __forceinline__ float erfinv_xla(float x) {
    float xx = x * x;
    float w = -log1pf(-xx);
    float p;
    if (w < 5.0f) {
        w = w - 2.5f;
        p = 2.81022636e-08f;
        p = fmaf(p, w, 3.43273939e-07f);
        p = fmaf(p, w, -3.5233877e-06f);
        p = fmaf(p, w, -4.39150654e-06f);
        p = fmaf(p, w, 0.00021858087f);
        p = fmaf(p, w, -0.00125372503f);
        p = fmaf(p, w, -0.00417768164f);
        p = fmaf(p, w, 0.246640727f);
        p = fmaf(p, w, 1.50140941f);
    } else {
        w = __fsqrt_rn(w) - 3.0f;
        p = -0.000200214257f;
        p = fmaf(p, w, 0.000100950558f);
        p = fmaf(p, w, 0.00134934322f);
        p = fmaf(p, w, -0.00367342844f);
        p = fmaf(p, w, 0.00573950773f);
        p = fmaf(p, w, -0.0076224613f);
        p = fmaf(p, w, 0.00943887047f);
        p = fmaf(p, w, 1.00167406f);
        p = fmaf(p, w, 2.83297682f);
    }
    return p * x;
}

// ---------------- f32x2 packed helpers (Blackwell) --------------------------
typedef unsigned long long ull;
__device__ __forceinline__ ull pk2(float a, float b) {
    ull r; asm("mov.b64 %0, {%1, %2};" : "=l"(r) : "f"(a), "f"(b)); return r;
}
__device__ __forceinline__ void upk2(float& a, float& b, ull v) {
    asm("mov.b64 {%0, %1}, %2;" : "=f"(a), "=f"(b) : "l"(v));
}
__device__ __forceinline__ ull cst2(float c) {
    uint32_t u = __float_as_uint(c);
    return ((ull)u << 32) | (ull)u;
}
#define FMA2(d, a, b, c) asm("fma.rn.f32x2 %0, %1, %2, %3;" : "=l"(d) : "l"(a), "l"(b), "l"(c))
#define MUL2(d, a, b)    asm("mul.rn.f32x2 %0, %1, %2;"     : "=l"(d) : "l"(a), "l"(b))
#define ADD2(d, a, b)    asm("add.rn.f32x2 %0, %1, %2;"     : "=l"(d) : "l"(a), "l"(b))
// d = a - b  (one FMA2: a + (-1)*b)
#define SUB2(d, a, b)    asm("fma.rn.f32x2 %0, %1, %2, %3;" : "=l"(d) : "l"(b), "l"(0xBF800000BF800000ULL), "l"(a))

__device__ __forceinline__ float rcp_approx(float x) {
    float r; asm("rcp.approx.f32 %0, %1;" : "=f"(r) : "f"(x)); return r;
}

// packed tanh over a f32x2 pair; XLA polynomial, rcp+NR division
__device__ __forceinline__ ull tanh2p(ull Xin) {
    float xa, xb; upk2(xa, xb, Xin);
    const float kClamp = 7.99881172180175781f;
    float ca_ = fminf(fmaxf(xa, -kClamp), kClamp);
    float cb_ = fminf(fmaxf(xb, -kClamp), kClamp);
    ull X = pk2(ca_, cb_);
    ull X2; MUL2(X2, X, X);
    ull P;
    FMA2(P, X2, cst2(-2.76076847742355e-16f), cst2(2.00018790482477e-13f));
    FMA2(P, X2, P, cst2(-8.60467152213735e-11f));
    FMA2(P, X2, P, cst2(5.12229709037114e-08f));
    FMA2(P, X2, P, cst2(1.48572235717979e-05f));
    FMA2(P, X2, P, cst2(6.37261928875436e-04f));
    FMA2(P, X2, P, cst2(4.89352455891786e-03f));
    MUL2(P, X, P);
    ull Q;
    FMA2(Q, X2, cst2(1.19825839466702e-06f), cst2(1.18534705686654e-04f));
    FMA2(Q, X2, Q, cst2(2.26843463243900e-03f));
    FMA2(Q, X2, Q, cst2(4.89352518554385e-03f));
    float qa, qb; upk2(qa, qb, Q);
    ull R0 = pk2(rcp_approx(qa), rcp_approx(qb));
    ull NQ = pk2(-qa, -qb);
    ull T; FMA2(T, NQ, R0, cst2(2.0f));     // 2 - q*r
    ull R1; MUL2(R1, R0, T);                // Newton step
    ull RES; MUL2(RES, P, R1);
    float va, vb; upk2(va, vb, RES);
    float ra = (fabsf(xa) < 0.0004f) ? xa : va;
    float rb = (fabsf(xb) < 0.0004f) ? xb : vb;
    return pk2(ra, rb);
}

// dot of two packed pairs with packed weights -> scalar contribution
__device__ __forceinline__ float dot4(ull t01, ull t23, ull w01, ull w23) {
    ull m0; MUL2(m0, t01, w01);
    ull m1; MUL2(m1, t23, w23);
    float a, b, c, d;
    upk2(a, b, m0); upk2(c, d, m1);
    return (a + b) + (c + d);
}

// ---------------- kernel 1: precompute all noise / uniforms ----------------
__global__ void __launch_bounds__(256) noise_kernel() {
    const int t = blockIdx.x;
    const int tid = threadIdx.x;

    uint32_t kt0, kt1;
    tf2x32(0u, 1u, 0u, (uint32_t)t, kt0, kt1);

    uint32_t n0, n1, u0, u1;
    tf2x32(kt0, kt1, 0u, 0u, n0, n1);   // k_noise
    tf2x32(kt0, kt1, 0u, 1u, u0, u1);   // k_unif

    const float LO = __uint_as_float(0xBF7FFFFFu);      // nextafter(-1,0)
    const float SQRT2 = __uint_as_float(0x3FB504F3u);   // f32(sqrt(2))
    const float STEP = 0.1f;

#pragma unroll
    for (int h = 0; h < 2; ++h) {
        int i = tid + h * 256;
        uint32_t b = rbits32(n0, n1, (uint32_t)i);
        float f = bits_to_unit(b);
        float u = fmaxf(LO, f * 2.0f + LO);
        float nv = SQRT2 * erfinv_xla(u);
        g_dx[t * DIMX + i] = nv * STEP;
    }

    if (tid == 0) {
        uint32_t b = rbits32(u0, u1, 0u);
        g_u[t] = bits_to_unit(b);
    }
}

// ---------------- kernel 2: dz[t][j] = dx[t] @ W1 --------------------------
__global__ void __launch_bounds__(256) dz_gemm(const float* __restrict__ W1) {
    __shared__ float dxs[GT * DIMX];            // 32 KB
    const int tx = threadIdx.x;
    const int j  = blockIdx.x * 256 + tx;
    const int t0 = blockIdx.y * GT;

    for (int k = tx; k < GT * DIMX; k += 256) dxs[k] = g_dx[t0 * DIMX + k];
    __syncthreads();

    float acc[GT];
#pragma unroll
    for (int q = 0; q < GT; ++q) acc[q] = 0.0f;

#pragma unroll 4
    for (int i = 0; i < DIMX; ++i) {
        float wv = W1[i * HID + j];
#pragma unroll
        for (int q = 0; q < GT; ++q)
            acc[q] = fmaf(wv, dxs[q * DIMX + i], acc[q]);
    }
#pragma unroll
    for (int q = 0; q < GT; ++q)
        g_dz[(t0 + q) * HID + j] = acc[q];
}

// ---------------- kernel 3: z0 = x0 @ W1 + b1 ------------------------------
__global__ void __launch_bounds__(256) z0_kernel(const float* __restrict__ x0,
                                                 const float* __restrict__ W1,
                                                 const float* __restrict__ b1) {
    __shared__ float xs[DIMX];
    const int tx = threadIdx.x;
    const int j  = blockIdx.x * 256 + tx;
    for (int k = tx; k < DIMX; k += 256) xs[k] = x0[k];
    __syncthreads();
    float acc = 0.0f;
    for (int i = 0; i < DIMX; ++i)
        acc = fmaf(xs[i], W1[i * HID + j], acc);
    g_z0[j] = acc + b1[j];
}

// ---------------- kernel 4: chain, ONE CTA, 256 thr, 2-step speculation ----
// Thread owns 4 contiguous hidden cols (two f32x2 pairs) and 2 x dims.
__global__ void __launch_bounds__(256, 1) chain_kernel(
    const float* __restrict__ x0, const float* __restrict__ W2,
    const float* __restrict__ b2, float* __restrict__ out)
{
    __shared__ float red[2][32];        // [parity][chain*8 + warp], 24 used
    __shared__ float us[NSTEP];

    const int tid  = threadIdx.x;
    const int lane = tid & 31;
    const int wid  = tid >> 5;          // 8 warps
    const int grp  = lane >> 3;         // 0..3 (8-lane groups)

    for (int k = tid; k < NSTEP; k += 256) us[k] = g_u[k];
    if (tid < 64) { red[0][tid & 31] = 0.0f; red[1][tid & 31] = 0.0f; }

    // per-thread column block: j4 = 4*tid
    const float4 z0v = *(const float4*)&g_z0[4 * tid];
    const float4 w2v = *(const float4*)&W2[4 * tid];
    ull zA = pk2(z0v.x, z0v.y), zB = pk2(z0v.z, z0v.w);
    ull cA = 0, cB = 0;                 // Kahan compensations (packed, start 0.0)
    const ull wA = pk2(w2v.x, w2v.y), wB = pk2(w2v.z, w2v.w);
    const float b2v = b2[0];
    float2 xr = *(const float2*)&x0[2 * tid];
    float p_old;

    __syncthreads();

    // ---- initial p_old = psi2(x0) ----
    {
        float y = dot4(tanh2p(zA), tanh2p(zB), wA, wB);
#pragma unroll
        for (int off = 16; off; off >>= 1)
            y += __shfl_xor_sync(0xffffffffu, y, off);
        if (lane == 0) red[0][wid] = y;
        __syncthreads();
        float s = red[0][lane & 7];
#pragma unroll
        for (int off = 4; off; off >>= 1)
            s += __shfl_xor_sync(0xffffffffu, s, off);
        float m = s + b2v;
        p_old = m * m;
        __syncthreads();
        if (tid < 32) red[0][tid] = 0.0f;
        __syncthreads();
    }

    // prefetch pair 0
    float4 dz0 = *(const float4*)&g_dz[0 * HID + 4 * tid];
    float4 dz1 = *(const float4*)&g_dz[1 * HID + 4 * tid];
    float2 dx0 = *(const float2*)&g_dx[0 * DIMX + 2 * tid];
    float2 dx1 = *(const float2*)&g_dx[1 * DIMX + 2 * tid];

    for (int m = 0; m < NPAIR; ++m) {
        const int t0 = 2 * m;
        const int par = m & 1;

        ull d0A = pk2(dz0.x, dz0.y), d0B = pk2(dz0.z, dz0.w);
        ull d1A = pk2(dz1.x, dz1.y), d1B = pk2(dz1.z, dz1.w);

        // candidates (packed Kahan replay)
        ull e0A; SUB2(e0A, d0A, cA);   ull e0B; SUB2(e0B, d0B, cB);
        ull v0A; ADD2(v0A, zA, e0A);   ull v0B; ADD2(v0B, zB, e0B);
        ull tA;  SUB2(tA, v0A, zA);    ull tB;  SUB2(tB, v0B, zB);
        ull c0A; SUB2(c0A, tA, e0A);   ull c0B; SUB2(c0B, tB, e0B);
        ull r1A; SUB2(r1A, d1A, cA);   ull r1B; SUB2(r1B, d1B, cB);
        ull v1rA; ADD2(v1rA, zA, r1A); ull v1rB; ADD2(v1rB, zB, r1B);
        ull a1A; SUB2(a1A, d1A, c0A);  ull a1B; SUB2(a1B, d1B, c0B);
        ull v1aA; ADD2(v1aA, v0A, a1A); ull v1aB; ADD2(v1aB, v0B, a1B);

        float y0  = dot4(tanh2p(v0A),  tanh2p(v0B),  wA, wB);
        float y1r = dot4(tanh2p(v1rA), tanh2p(v1rB), wA, wB);
        float y1a = dot4(tanh2p(v1aA), tanh2p(v1aB), wA, wB);

        // stage 1a: two shared butterfly levels on all three chains
#pragma unroll
        for (int off = 16; off >= 8; off >>= 1) {
            y0  += __shfl_xor_sync(0xffffffffu, y0,  off);
            y1r += __shfl_xor_sync(0xffffffffu, y1r, off);
            y1a += __shfl_xor_sync(0xffffffffu, y1a, off);
        }
        // redistribute: group g takes chain g (group 3 duplicates chain 2)
        float v = (grp == 0) ? y0 : (grp == 1) ? y1r : y1a;
        // stage 1b: finish within 8-lane groups
#pragma unroll
        for (int off = 4; off; off >>= 1)
            v += __shfl_xor_sync(0xffffffffu, v, off);
        if ((lane & 7) == 0 && grp < 3) red[par][grp * 8 + wid] = v;
        __syncthreads();

        // prefetch next pair (overlaps stage 2)
        float4 ndz0 = {}, ndz1 = {};
        float2 ndx0 = {}, ndx1 = {};
        if (m + 1 < NPAIR) {
            const int tn = 2 * m + 2;
            ndz0 = *(const float4*)&g_dz[tn * HID + 4 * tid];
            ndz1 = *(const float4*)&g_dz[(tn + 1) * HID + 4 * tid];
            ndx0 = *(const float2*)&g_dx[tn * DIMX + 2 * tid];
            ndx1 = *(const float2*)&g_dx[(tn + 1) * DIMX + 2 * tid];
        }

        // stage 2: every warp — 1 LDS + 3 group-butterflies + 3 broadcasts
        float tv = red[par][lane];              // lanes 24..31 read zeros
#pragma unroll
        for (int off = 4; off; off >>= 1)
            tv += __shfl_xor_sync(0xffffffffu, tv, off);
        float s0  = __shfl_sync(0xffffffffu, tv, 0);
        float s1r = __shfl_sync(0xffffffffu, tv, 8);
        float s1a = __shfl_sync(0xffffffffu, tv, 16);

        // decisions (uniform across all threads)
        float m0 = s0 + b2v;
        float p0 = m0 * m0;
        float r0 = fminf(__fdividef(p0, p_old + 1e-12f), 1.0f);
        bool a0 = us[t0] < r0;
        float pm = a0 ? p0 : p_old;
        float s1 = a0 ? s1a : s1r;
        float m1 = s1 + b2v;
        float p1 = m1 * m1;
        float r1 = fminf(__fdividef(p1, pm + 1e-12f), 1.0f);
        bool a1 = us[t0 + 1] < r1;
        p_old = a1 ? p1 : pm;

        // apply step t0
        if (a0) { zA = v0A; cA = c0A; zB = v0B; cB = c0B;
                  xr.x += dx0.x; xr.y += dx0.y; }
        if (t0 >= BURN) *(float2*)&out[(t0 - BURN) * DIMX + 2 * tid] = xr;
        // apply step t1
        if (a1) {
            ull eA; SUB2(eA, d1A, cA);  ull znA; ADD2(znA, zA, eA);
            ull uA; SUB2(uA, znA, zA);  SUB2(cA, uA, eA);  zA = znA;
            ull eB; SUB2(eB, d1B, cB);  ull znB; ADD2(znB, zB, eB);
            ull uB; SUB2(uB, znB, zB);  SUB2(cB, uB, eB);  zB = znB;
            xr.x += dx1.x; xr.y += dx1.y;
        }
        if (t0 + 1 >= BURN) *(float2*)&out[(t0 + 1 - BURN) * DIMX + 2 * tid] = xr;

        dz0 = ndz0; dz1 = ndz1; dx0 = ndx0; dx1 = ndx1;
    }
}

// ---------------- launch ----------------------------------------------------
extern "C" void kernel_launch(void* const* d_in, const int* in_sizes, int n_in,
                              void* d_out, int out_size) {
    const float* x0 = (const float*)d_in[0];
    const float* W1 = (const float*)d_in[1];
    const float* b1 = (const float*)d_in[2];
    const float* W2 = (const float*)d_in[3];
    const float* b2 = (const float*)d_in[4];
    float* out = (float*)d_out;

    noise_kernel<<<NSTEP, 256>>>();
    dz_gemm<<<dim3(HID / 256, NSTEP / GT), 256>>>(W1);
    z0_kernel<<<HID / 256, 256>>>(x0, W1, b1);
    chain_kernel<<<1, 256>>>(x0, W2, b2, out);
}

// round 8
// speedup vs baseline: 1.3962x; 1.3962x over previous
#include <cuda_runtime.h>
#include <cstdint>

#define NSTEP 2176
#define NPAIR (NSTEP / 2)
#define BURN  128
#define DIMX  512
#define HID   1024
#define GT    16            // t-tile for dz GEMM

// ---------------- scratch (device globals: no allocation allowed) ----------
__device__ float g_dx[NSTEP * DIMX];   // scaled noise: normal * 0.1
__device__ float g_u [NSTEP];          // per-step uniforms
__device__ float g_dz[NSTEP * HID];    // dz[t][j] = sum_i dx[t][i] * W1[i][j]
__device__ float g_z0[HID];            // z0 = x0 @ W1 + b1

// ---------------- threefry2x32 (JAX-exact, partitionable) ------------------
__device__ __forceinline__ uint32_t rotl32(uint32_t v, int r) {
    return (v << r) | (v >> (32 - r));
}
__device__ __forceinline__ void tf2x32(uint32_t k0, uint32_t k1,
                                       uint32_t x0, uint32_t x1,
                                       uint32_t& o0, uint32_t& o1) {
    uint32_t k2 = k0 ^ k1 ^ 0x1BD11BDAu;
    x0 += k0; x1 += k1;
#define TF_R(R) { x0 += x1; x1 = rotl32(x1, R); x1 ^= x0; }
    TF_R(13) TF_R(15) TF_R(26) TF_R(6)
    x0 += k1; x1 += k2 + 1u;
    TF_R(17) TF_R(29) TF_R(16) TF_R(24)
    x0 += k2; x1 += k0 + 2u;
    TF_R(13) TF_R(15) TF_R(26) TF_R(6)
    x0 += k0; x1 += k1 + 3u;
    TF_R(17) TF_R(29) TF_R(16) TF_R(24)
    x0 += k1; x1 += k2 + 4u;
    TF_R(13) TF_R(15) TF_R(26) TF_R(6)
    x0 += k2; x1 += k0 + 5u;
#undef TF_R
    o0 = x0; o1 = x1;
}

__device__ __forceinline__ uint32_t rbits32(uint32_t k0, uint32_t k1, uint32_t idx) {
    uint32_t o0, o1;
    tf2x32(k0, k1, 0u, idx, o0, o1);
    return o0 ^ o1;
}

__device__ __forceinline__ float bits_to_unit(uint32_t b) {
    return __uint_as_float((b >> 9) | 0x3f800000u) - 1.0f;
}

// XLA ErfInv32 (Giles). log1pf == libdevice __nv_log1pf == what XLA emits.
__device__ __forceinline__ float erfinv_xla(float x) {
    float xx = x * x;
    float w = -log1pf(-xx);
    float p;
    if (w < 5.0f) {
        w = w - 2.5f;
        p = 2.81022636e-08f;
        p = fmaf(p, w, 3.43273939e-07f);
        p = fmaf(p, w, -3.5233877e-06f);
        p = fmaf(p, w, -4.39150654e-06f);
        p = fmaf(p, w, 0.00021858087f);
        p = fmaf(p, w, -0.00125372503f);
        p = fmaf(p, w, -0.00417768164f);
        p = fmaf(p, w, 0.246640727f);
        p = fmaf(p, w, 1.50140941f);
    } else {
        w = __fsqrt_rn(w) - 3.0f;
        p = -0.000200214257f;
        p = fmaf(p, w, 0.000100950558f);
        p = fmaf(p, w, 0.00134934322f);
        p = fmaf(p, w, -0.00367342844f);
        p = fmaf(p, w, 0.00573950773f);
        p = fmaf(p, w, -0.0076224613f);
        p = fmaf(p, w, 0.00943887047f);
        p = fmaf(p, w, 1.00167406f);
        p = fmaf(p, w, 2.83297682f);
    }
    return p * x;
}

// ---------------- f32x2 packed helpers (Blackwell) --------------------------
typedef unsigned long long ull;
__device__ __forceinline__ ull pk2(float a, float b) {
    ull r; asm("mov.b64 %0, {%1, %2};" : "=l"(r) : "f"(a), "f"(b)); return r;
}
__device__ __forceinline__ void upk2(float& a, float& b, ull v) {
    asm("mov.b64 {%0, %1}, %2;" : "=f"(a), "=f"(b) : "l"(v));
}
__device__ __forceinline__ ull cst2(float c) {
    uint32_t u = __float_as_uint(c);
    return ((ull)u << 32) | (ull)u;
}
#define FMA2(d, a, b, c) asm("fma.rn.f32x2 %0, %1, %2, %3;" : "=l"(d) : "l"(a), "l"(b), "l"(c))
#define MUL2(d, a, b)    asm("mul.rn.f32x2 %0, %1, %2;"     : "=l"(d) : "l"(a), "l"(b))

__device__ __forceinline__ float rcp_approx(float x) {
    float r; asm("rcp.approx.f32 %0, %1;" : "=f"(r) : "f"(x)); return r;
}

// packed tanh over two columns; XLA polynomial, fast rcp+NR division
__device__ __forceinline__ void tanh2(float xa, float xb, float& ra, float& rb) {
    const float kClamp = 7.99881172180175781f;
    float ca_ = fminf(fmaxf(xa, -kClamp), kClamp);
    float cb_ = fminf(fmaxf(xb, -kClamp), kClamp);
    ull X = pk2(ca_, cb_);
    ull X2; MUL2(X2, X, X);
    ull P;
    FMA2(P, X2, cst2(-2.76076847742355e-16f), cst2(2.00018790482477e-13f));
    FMA2(P, X2, P, cst2(-8.60467152213735e-11f));
    FMA2(P, X2, P, cst2(5.12229709037114e-08f));
    FMA2(P, X2, P, cst2(1.48572235717979e-05f));
    FMA2(P, X2, P, cst2(6.37261928875436e-04f));
    FMA2(P, X2, P, cst2(4.89352455891786e-03f));
    MUL2(P, X, P);
    ull Q;
    FMA2(Q, X2, cst2(1.19825839466702e-06f), cst2(1.18534705686654e-04f));
    FMA2(Q, X2, Q, cst2(2.26843463243900e-03f));
    FMA2(Q, X2, Q, cst2(4.89352518554385e-03f));
    float qa, qb; upk2(qa, qb, Q);
    ull R0 = pk2(rcp_approx(qa), rcp_approx(qb));
    ull NQ = pk2(-qa, -qb);
    ull T; FMA2(T, NQ, R0, cst2(2.0f));     // 2 - q*r
    ull R1; MUL2(R1, R0, T);                // Newton step
    ull RES; MUL2(RES, P, R1);
    float va, vb; upk2(va, vb, RES);
    ra = (fabsf(xa) < 0.0004f) ? xa : va;
    rb = (fabsf(xb) < 0.0004f) ? xb : vb;
}

// ---------------- kernel 1: precompute all noise / uniforms ----------------
__global__ void __launch_bounds__(256) noise_kernel() {
    const int t = blockIdx.x;
    const int tid = threadIdx.x;

    uint32_t kt0, kt1;
    tf2x32(0u, 1u, 0u, (uint32_t)t, kt0, kt1);

    uint32_t n0, n1, u0, u1;
    tf2x32(kt0, kt1, 0u, 0u, n0, n1);   // k_noise
    tf2x32(kt0, kt1, 0u, 1u, u0, u1);   // k_unif

    const float LO = __uint_as_float(0xBF7FFFFFu);      // nextafter(-1,0)
    const float SQRT2 = __uint_as_float(0x3FB504F3u);   // f32(sqrt(2))
    const float STEP = 0.1f;

#pragma unroll
    for (int h = 0; h < 2; ++h) {
        int i = tid + h * 256;
        uint32_t b = rbits32(n0, n1, (uint32_t)i);
        float f = bits_to_unit(b);
        float u = fmaxf(LO, f * 2.0f + LO);
        float nv = SQRT2 * erfinv_xla(u);
        g_dx[t * DIMX + i] = nv * STEP;
    }

    if (tid == 0) {
        uint32_t b = rbits32(u0, u1, 0u);
        g_u[t] = bits_to_unit(b);
    }
}

// ---------------- kernel 2: dz[t][j] = dx[t] @ W1 (packed t-pairs) ---------
__global__ void __launch_bounds__(256) dz_gemm(const float* __restrict__ W1) {
    __shared__ float dxs[GT * DIMX];            // 32 KB
    const int tx = threadIdx.x;
    const int j  = blockIdx.x * 256 + tx;
    const int t0 = blockIdx.y * GT;

    for (int k = tx; k < GT * DIMX; k += 256) dxs[k] = g_dx[t0 * DIMX + k];
    __syncthreads();

    ull acc[GT / 2];
#pragma unroll
    for (int q = 0; q < GT / 2; ++q) acc[q] = 0;

#pragma unroll 4
    for (int i = 0; i < DIMX; ++i) {
        float wv = W1[i * HID + j];
        ull WV = pk2(wv, wv);
#pragma unroll
        for (int q = 0; q < GT / 2; ++q) {
            ull DX = pk2(dxs[(2 * q) * DIMX + i], dxs[(2 * q + 1) * DIMX + i]);
            FMA2(acc[q], WV, DX, acc[q]);
        }
    }
#pragma unroll
    for (int q = 0; q < GT / 2; ++q) {
        float a, b; upk2(a, b, acc[q]);
        g_dz[(t0 + 2 * q) * HID + j] = a;
        g_dz[(t0 + 2 * q + 1) * HID + j] = b;
    }
}

// ---------------- kernel 3: z0 = x0 @ W1 + b1 ------------------------------
__global__ void __launch_bounds__(256) z0_kernel(const float* __restrict__ x0,
                                                 const float* __restrict__ W1,
                                                 const float* __restrict__ b1) {
    __shared__ float xs[DIMX];
    const int tx = threadIdx.x;
    const int j  = blockIdx.x * 256 + tx;
    for (int k = tx; k < DIMX; k += 256) xs[k] = x0[k];
    __syncthreads();
    float acc = 0.0f;
    for (int i = 0; i < DIMX; ++i)
        acc = fmaf(xs[i], W1[i * HID + j], acc);
    g_z0[j] = acc + b1[j];
}

// ---------------- kernel 4: chain, ONE CTA, 512 thr, 2-step speculation ----
__global__ void __launch_bounds__(512, 1) chain_kernel(
    const float* __restrict__ x0, const float* __restrict__ W2,
    const float* __restrict__ b2, float* __restrict__ out)
{
    __shared__ float red[2][48];        // [parity][chain*16 + warp]
    __shared__ float us[NSTEP];

    const int tid  = threadIdx.x;
    const int lane = tid & 31;
    const int wid  = tid >> 5;          // 16 warps
    const int grp  = lane >> 3;         // 0..3 (8-lane groups)

    for (int k = tid; k < NSTEP; k += 512) us[k] = g_u[k];

    float za = g_z0[tid], zb = g_z0[tid + DIMX];   // b1 folded in
    float ca = 0.0f, cb = 0.0f;                    // Kahan compensations
    const float W2a = W2[tid], W2b = W2[tid + DIMX];
    const float b2v = b2[0];
    float xr = x0[tid];
    float p_old;

    // ---- initial p_old = psi2(x0) ----
    {
        float ta, tb; tanh2(za, zb, ta, tb);
        float y = ta * W2a + tb * W2b;
#pragma unroll
        for (int off = 16; off; off >>= 1)
            y += __shfl_xor_sync(0xffffffffu, y, off);
        if (lane == 0) red[1][wid] = y;
        __syncthreads();
        float s = red[1][lane & 15];
#pragma unroll
        for (int off = 8; off; off >>= 1)
            s += __shfl_xor_sync(0xffffffffu, s, off);
        float m = s + b2v;
        p_old = m * m;
        __syncthreads();
    }

    // prefetch pair 0
    float dz0a = g_dz[0 * HID + tid], dz0b = g_dz[0 * HID + tid + DIMX];
    float dz1a = g_dz[1 * HID + tid], dz1b = g_dz[1 * HID + tid + DIMX];
    float dx0 = g_dx[0 * DIMX + tid], dx1 = g_dx[1 * DIMX + tid];

    for (int m = 0; m < NPAIR; ++m) {
        const int t0 = 2 * m;
        const int par = m & 1;

        // candidates (bitwise replay of the sequential Kahan recurrence)
        float e0a = dz0a - ca,  e0b = dz0b - cb;
        float v0a = za + e0a,   v0b = zb + e0b;            // step t0 / accept-z
        float c0pa = (v0a - za) - e0a;
        float c0pb = (v0b - zb) - e0b;
        float v1ra = za + (dz1a - ca),   v1rb = zb + (dz1b - cb);    // t1 | reject
        float v1aa = v0a + (dz1a - c0pa), v1ab = v0b + (dz1b - c0pb); // t1 | accept

        float t0a, t0b, t1ra_, t1rb_, t1aa_, t1ab_;
        tanh2(v0a,  v0b,  t0a,   t0b);
        tanh2(v1ra, v1rb, t1ra_, t1rb_);
        tanh2(v1aa, v1ab, t1aa_, t1ab_);
        float y0  = t0a   * W2a + t0b   * W2b;
        float y1r = t1ra_ * W2a + t1rb_ * W2b;
        float y1a = t1aa_ * W2a + t1ab_ * W2b;

        // stage 1a: two shared butterfly levels (lanes end up holding their
        // (lane&7)-coset sums, identical across the four 8-lane groups)
#pragma unroll
        for (int off = 16; off >= 8; off >>= 1) {
            y0  += __shfl_xor_sync(0xffffffffu, y0,  off);
            y1r += __shfl_xor_sync(0xffffffffu, y1r, off);
            y1a += __shfl_xor_sync(0xffffffffu, y1a, off);
        }
        // redistribute: group g finishes chain g (group 3 duplicates chain 2)
        float v = (grp == 0) ? y0 : (grp == 1) ? y1r : y1a;
#pragma unroll
        for (int off = 4; off; off >>= 1)
            v += __shfl_xor_sync(0xffffffffu, v, off);
        if ((lane & 7) == 0 && grp < 3) red[par][grp * 16 + wid] = v;
        __syncthreads();

        // prefetch next pair (overlaps stage 2)
        float ndz0a = 0.f, ndz0b = 0.f, ndz1a = 0.f, ndz1b = 0.f;
        float ndx0 = 0.f, ndx1 = 0.f;
        if (m + 1 < NPAIR) {
            const int tn = 2 * m + 2;
            ndz0a = g_dz[tn * HID + tid];       ndz0b = g_dz[tn * HID + tid + DIMX];
            ndz1a = g_dz[(tn + 1) * HID + tid]; ndz1b = g_dz[(tn + 1) * HID + tid + DIMX];
            ndx0  = g_dx[tn * DIMX + tid];      ndx1  = g_dx[(tn + 1) * DIMX + tid];
        }

        // stage 2: chains 0+1 in one register (16-lane halves), chain 2 in a second
        float tv  = red[par][lane];             // lanes 0-15: chain0, 16-31: chain1
        float tv2 = red[par][32 + (lane & 15)]; // chain 2
#pragma unroll
        for (int off = 8; off; off >>= 1) {
            tv  += __shfl_xor_sync(0xffffffffu, tv,  off);
            tv2 += __shfl_xor_sync(0xffffffffu, tv2, off);
        }
        float s0  = __shfl_sync(0xffffffffu, tv, 0);
        float s1r = __shfl_sync(0xffffffffu, tv, 16);
        float s1a = tv2;                        // all lanes already hold it

        // decisions (uniform across all threads)
        float m0 = s0 + b2v;
        float p0 = m0 * m0;
        float r0 = fminf(__fdividef(p0, p_old + 1e-12f), 1.0f);
        bool a0 = us[t0] < r0;
        float pm = a0 ? p0 : p_old;
        float s1 = a0 ? s1a : s1r;
        float m1 = s1 + b2v;
        float p1 = m1 * m1;
        float r1 = fminf(__fdividef(p1, pm + 1e-12f), 1.0f);
        bool a1 = us[t0 + 1] < r1;
        p_old = a1 ? p1 : pm;

        // apply step t0
        if (a0) { za = v0a; ca = c0pa; zb = v0b; cb = c0pb; xr += dx0; }
        if (t0 >= BURN) out[(t0 - BURN) * DIMX + tid] = xr;
        // apply step t1
        if (a1) {
            float ea = dz1a - ca;  float zn = za + ea;  ca = (zn - za) - ea;  za = zn;
            float eb = dz1b - cb;  float zm = zb + eb;  cb = (zm - zb) - eb;  zb = zm;
            xr += dx1;
        }
        if (t0 + 1 >= BURN) out[(t0 + 1 - BURN) * DIMX + tid] = xr;

        dz0a = ndz0a; dz0b = ndz0b; dz1a = ndz1a; dz1b = ndz1b;
        dx0 = ndx0; dx1 = ndx1;
    }
}

// ---------------- launch ----------------------------------------------------
extern "C" void kernel_launch(void* const* d_in, const int* in_sizes, int n_in,
                              void* d_out, int out_size) {
    const float* x0 = (const float*)d_in[0];
    const float* W1 = (const float*)d_in[1];
    const float* b1 = (const float*)d_in[2];
    const float* W2 = (const float*)d_in[3];
    const float* b2 = (const float*)d_in[4];
    float* out = (float*)d_out;

    noise_kernel<<<NSTEP, 256>>>();
    dz_gemm<<<dim3(HID / 256, NSTEP / GT), 256>>>(W1);
    z0_kernel<<<HID / 256, 256>>>(x0, W1, b1);
    chain_kernel<<<1, 512>>>(x0, W2, b2, out);
}

// round 9
// speedup vs baseline: 1.5967x; 1.1436x over previous
#include <cuda_runtime.h>
#include <cstdint>

#define NSTEP 2176
#define NPAIR (NSTEP / 2)
#define BURN  128
#define DIMX  512
#define HID   1024
#define GT    16            // t-tile for dz GEMM

// ---------------- scratch (device globals: no allocation allowed) ----------
__device__ float g_dx[NSTEP * DIMX];   // scaled noise: normal * 0.1
__device__ float g_u [NSTEP];          // per-step uniforms
__device__ float g_dz[NSTEP * HID];    // dz[t][j] = sum_i dx[t][i] * W1[i][j]
__device__ float g_z0[HID];            // z0 = x0 @ W1 + b1

// ---------------- threefry2x32 (JAX-exact, partitionable) ------------------
__device__ __forceinline__ uint32_t rotl32(uint32_t v, int r) {
    return (v << r) | (v >> (32 - r));
}
__device__ __forceinline__ void tf2x32(uint32_t k0, uint32_t k1,
                                       uint32_t x0, uint32_t x1,
                                       uint32_t& o0, uint32_t& o1) {
    uint32_t k2 = k0 ^ k1 ^ 0x1BD11BDAu;
    x0 += k0; x1 += k1;
#define TF_R(R) { x0 += x1; x1 = rotl32(x1, R); x1 ^= x0; }
    TF_R(13) TF_R(15) TF_R(26) TF_R(6)
    x0 += k1; x1 += k2 + 1u;
    TF_R(17) TF_R(29) TF_R(16) TF_R(24)
    x0 += k2; x1 += k0 + 2u;
    TF_R(13) TF_R(15) TF_R(26) TF_R(6)
    x0 += k0; x1 += k1 + 3u;
    TF_R(17) TF_R(29) TF_R(16) TF_R(24)
    x0 += k1; x1 += k2 + 4u;
    TF_R(13) TF_R(15) TF_R(26) TF_R(6)
    x0 += k2; x1 += k0 + 5u;
#undef TF_R
    o0 = x0; o1 = x1;
}

__device__ __forceinline__ uint32_t rbits32(uint32_t k0, uint32_t k1, uint32_t idx) {
    uint32_t o0, o1;
    tf2x32(k0, k1, 0u, idx, o0, o1);
    return o0 ^ o1;
}

__device__ __forceinline__ float bits_to_unit(uint32_t b) {
    return __uint_as_float((b >> 9) | 0x3f800000u) - 1.0f;
}

// XLA ErfInv32 (Giles). log1pf == libdevice __nv_log1pf == what XLA emits.
__device__ __forceinline__ float erfinv_xla(float x) {
    float xx = x * x;
    float w = -log1pf(-xx);
    float p;
    if (w < 5.0f) {
        w = w - 2.5f;
        p = 2.81022636e-08f;
        p = fmaf(p, w, 3.43273939e-07f);
        p = fmaf(p, w, -3.5233877e-06f);
        p = fmaf(p, w, -4.39150654e-06f);
        p = fmaf(p, w, 0.00021858087f);
        p = fmaf(p, w, -0.00125372503f);
        p = fmaf(p, w, -0.00417768164f);
        p = fmaf(p, w, 0.246640727f);
        p = fmaf(p, w, 1.50140941f);
    } else {
        w = __fsqrt_rn(w) - 3.0f;
        p = -0.000200214257f;
        p = fmaf(p, w, 0.000100950558f);
        p = fmaf(p, w, 0.00134934322f);
        p = fmaf(p, w, -0.00367342844f);
        p = fmaf(p, w, 0.00573950773f);
        p = fmaf(p, w, -0.0076224613f);
        p = fmaf(p, w, 0.00943887047f);
        p = fmaf(p, w, 1.00167406f);
        p = fmaf(p, w, 2.83297682f);
    }
    return p * x;
}

// ---------------- f32x2 packed helpers (Blackwell) --------------------------
typedef unsigned long long ull;
__device__ __forceinline__ ull pk2(float a, float b) {
    ull r; asm("mov.b64 %0, {%1, %2};" : "=l"(r) : "f"(a), "f"(b)); return r;
}
__device__ __forceinline__ void upk2(float& a, float& b, ull v) {
    asm("mov.b64 {%0, %1}, %2;" : "=f"(a), "=f"(b) : "l"(v));
}
__device__ __forceinline__ ull cst2(float c) {
    uint32_t u = __float_as_uint(c);
    return ((ull)u << 32) | (ull)u;
}
#define FMA2(d, a, b, c) asm("fma.rn.f32x2 %0, %1, %2, %3;" : "=l"(d) : "l"(a), "l"(b), "l"(c))
#define MUL2(d, a, b)    asm("mul.rn.f32x2 %0, %1, %2;"     : "=l"(d) : "l"(a), "l"(b))
#define ADD2(d, a, b)    asm("add.rn.f32x2 %0, %1, %2;"     : "=l"(d) : "l"(a), "l"(b))
// d = a - b  (one FMA2: a + (-1)*b)
#define SUB2(d, a, b)    asm("fma.rn.f32x2 %0, %1, %2, %3;" : "=l"(d) : "l"(b), "l"(0xBF800000BF800000ULL), "l"(a))

__device__ __forceinline__ float rcp_approx(float x) {
    float r; asm("rcp.approx.f32 %0, %1;" : "=f"(r) : "f"(x)); return r;
}
__device__ __forceinline__ float ex2_approx(float x) {
    float r; asm("ex2.approx.f32 %0, %1;" : "=f"(r) : "f"(x)); return r;
}

// MUFU-pipe tanh over a packed pair: tanh(x) = 1 - 2/(e^{2x}+1)
// 3 f32x2 FMA-pipe ops + 4 MUFU ops per 2 columns.
// Edge cases: x large + -> E=inf -> r=0 -> t=1;  x large - -> E=0 -> t=-1.
__device__ __forceinline__ void tanh2_mufu(ull X, float& ra, float& rb) {
    ull S; MUL2(S, X, cst2(2.8853900817779268f));   // 2*log2(e)*x
    float sa, sb; upk2(sa, sb, S);
    float Ea = ex2_approx(sa), Eb = ex2_approx(sb); // e^{2x}
    ull D; ADD2(D, pk2(Ea, Eb), cst2(1.0f));
    float da, db; upk2(da, db, D);
    ull R = pk2(rcp_approx(da), rcp_approx(db));
    ull T; FMA2(T, R, cst2(-2.0f), cst2(1.0f));
    upk2(ra, rb, T);
}

// ---------------- kernel 1: precompute all noise / uniforms ----------------
__global__ void __launch_bounds__(256) noise_kernel() {
    const int t = blockIdx.x;
    const int tid = threadIdx.x;

    uint32_t kt0, kt1;
    tf2x32(0u, 1u, 0u, (uint32_t)t, kt0, kt1);

    uint32_t n0, n1, u0, u1;
    tf2x32(kt0, kt1, 0u, 0u, n0, n1);   // k_noise
    tf2x32(kt0, kt1, 0u, 1u, u0, u1);   // k_unif

    const float LO = __uint_as_float(0xBF7FFFFFu);      // nextafter(-1,0)
    const float SQRT2 = __uint_as_float(0x3FB504F3u);   // f32(sqrt(2))
    const float STEP = 0.1f;

#pragma unroll
    for (int h = 0; h < 2; ++h) {
        int i = tid + h * 256;
        uint32_t b = rbits32(n0, n1, (uint32_t)i);
        float f = bits_to_unit(b);
        float u = fmaxf(LO, f * 2.0f + LO);
        float nv = SQRT2 * erfinv_xla(u);
        g_dx[t * DIMX + i] = nv * STEP;
    }

    if (tid == 0) {
        uint32_t b = rbits32(u0, u1, 0u);
        g_u[t] = bits_to_unit(b);
    }
}

// ---------------- kernel 2: dz[t][j] = dx[t] @ W1 (packed t-pairs) ---------
__global__ void __launch_bounds__(256) dz_gemm(const float* __restrict__ W1) {
    __shared__ float dxs[GT * DIMX];            // 32 KB
    const int tx = threadIdx.x;
    const int j  = blockIdx.x * 256 + tx;
    const int t0 = blockIdx.y * GT;

    for (int k = tx; k < GT * DIMX; k += 256) dxs[k] = g_dx[t0 * DIMX + k];
    __syncthreads();

    ull acc[GT / 2];
#pragma unroll
    for (int q = 0; q < GT / 2; ++q) acc[q] = 0;

#pragma unroll 4
    for (int i = 0; i < DIMX; ++i) {
        float wv = W1[i * HID + j];
        ull WV = pk2(wv, wv);
#pragma unroll
        for (int q = 0; q < GT / 2; ++q) {
            ull DX = pk2(dxs[(2 * q) * DIMX + i], dxs[(2 * q + 1) * DIMX + i]);
            FMA2(acc[q], WV, DX, acc[q]);
        }
    }
#pragma unroll
    for (int q = 0; q < GT / 2; ++q) {
        float a, b; upk2(a, b, acc[q]);
        g_dz[(t0 + 2 * q) * HID + j] = a;
        g_dz[(t0 + 2 * q + 1) * HID + j] = b;
    }
}

// ---------------- kernel 3: z0 = x0 @ W1 + b1 ------------------------------
__global__ void __launch_bounds__(256) z0_kernel(const float* __restrict__ x0,
                                                 const float* __restrict__ W1,
                                                 const float* __restrict__ b1) {
    __shared__ float xs[DIMX];
    const int tx = threadIdx.x;
    const int j  = blockIdx.x * 256 + tx;
    for (int k = tx; k < DIMX; k += 256) xs[k] = x0[k];
    __syncthreads();
    float acc = 0.0f;
    for (int i = 0; i < DIMX; ++i)
        acc = fmaf(xs[i], W1[i * HID + j], acc);
    g_z0[j] = acc + b1[j];
}

// ---------------- kernel 4: chain, ONE CTA, 512 thr, 2-step speculation ----
// Thread owns hidden cols (tid, tid+512) packed as one f32x2, and x dim tid.
__global__ void __launch_bounds__(512, 1) chain_kernel(
    const float* __restrict__ x0, const float* __restrict__ W2,
    const float* __restrict__ b2, float* __restrict__ out)
{
    __shared__ float red[2][3][16];     // [parity][chain][warp]
    __shared__ float us[NSTEP];

    const int tid  = threadIdx.x;
    const int lane = tid & 31;
    const int wid  = tid >> 5;          // 16 warps

    for (int k = tid; k < NSTEP; k += 512) us[k] = g_u[k];

    ull zP = pk2(g_z0[tid], g_z0[tid + DIMX]);   // b1 folded in
    ull cP = 0;                                   // Kahan compensation (0.0,0.0)
    const float W2a = W2[tid], W2b = W2[tid + DIMX];
    const float b2v = b2[0];
    float xr = x0[tid];
    float p_old;

    // ---- initial p_old = psi2(x0) ----
    {
        float ta, tb; tanh2_mufu(zP, ta, tb);
        float y = fmaf(tb, W2b, ta * W2a);
#pragma unroll
        for (int off = 16; off; off >>= 1)
            y += __shfl_xor_sync(0xffffffffu, y, off);
        if (lane == 0) red[1][0][wid] = y;
        __syncthreads();
        float s = red[1][0][lane & 15];
#pragma unroll
        for (int off = 8; off; off >>= 1)
            s += __shfl_xor_sync(0xffffffffu, s, off);
        float m = s + b2v;
        p_old = m * m;
        __syncthreads();
    }

    // prefetch pair 0
    ull d0 = pk2(g_dz[0 * HID + tid], g_dz[0 * HID + tid + DIMX]);
    ull d1 = pk2(g_dz[1 * HID + tid], g_dz[1 * HID + tid + DIMX]);
    float dx0 = g_dx[0 * DIMX + tid], dx1 = g_dx[1 * DIMX + tid];

    for (int m = 0; m < NPAIR; ++m) {
        const int t0 = 2 * m;
        const int par = m & 1;

        // candidates (packed bitwise replay of the sequential Kahan recurrence)
        ull e0;  SUB2(e0, d0, cP);
        ull v0;  ADD2(v0, zP, e0);          // step t0 arg / accept-z
        ull tt;  SUB2(tt, v0, zP);
        ull c0;  SUB2(c0, tt, e0);
        ull r1;  SUB2(r1, d1, cP);
        ull v1r; ADD2(v1r, zP, r1);         // t1 | reject
        ull a1p; SUB2(a1p, d1, c0);
        ull v1a; ADD2(v1a, v0, a1p);        // t1 | accept

        float t0a, t0b, t1ra, t1rb, t1aa, t1ab;
        tanh2_mufu(v0,  t0a,  t0b);
        tanh2_mufu(v1r, t1ra, t1rb);
        tanh2_mufu(v1a, t1aa, t1ab);
        float y0  = fmaf(t0b,  W2b, t0a  * W2a);
        float y1r = fmaf(t1rb, W2b, t1ra * W2a);
        float y1a = fmaf(t1ab, W2b, t1aa * W2a);

        // stage 1: three interleaved intra-warp shuffle chains
#pragma unroll
        for (int off = 16; off; off >>= 1) {
            y0  += __shfl_xor_sync(0xffffffffu, y0,  off);
            y1r += __shfl_xor_sync(0xffffffffu, y1r, off);
            y1a += __shfl_xor_sync(0xffffffffu, y1a, off);
        }
        if (lane == 0) {
            red[par][0][wid] = y0;
            red[par][1][wid] = y1r;
            red[par][2][wid] = y1a;
        }
        __syncthreads();

        // prefetch next pair (overlaps stage 2)
        ull nd0 = 0, nd1 = 0;
        float ndx0 = 0.f, ndx1 = 0.f;
        if (m + 1 < NPAIR) {
            const int tn = 2 * m + 2;
            nd0 = pk2(g_dz[tn * HID + tid],       g_dz[tn * HID + tid + DIMX]);
            nd1 = pk2(g_dz[(tn + 1) * HID + tid], g_dz[(tn + 1) * HID + tid + DIMX]);
            ndx0 = g_dx[tn * DIMX + tid];
            ndx1 = g_dx[(tn + 1) * DIMX + tid];
        }

        // stage 2: every warp redundantly reduces the 16 partials
        int li = lane & 15;
        float s0  = red[par][0][li];
        float s1r = red[par][1][li];
        float s1a = red[par][2][li];
#pragma unroll
        for (int off = 8; off; off >>= 1) {
            s0  += __shfl_xor_sync(0xffffffffu, s0,  off);
            s1r += __shfl_xor_sync(0xffffffffu, s1r, off);
            s1a += __shfl_xor_sync(0xffffffffu, s1a, off);
        }

        // decisions (uniform across all threads)
        float m0 = s0 + b2v;
        float p0 = m0 * m0;
        float r0 = fminf(__fdividef(p0, p_old + 1e-12f), 1.0f);
        bool a0 = us[t0] < r0;
        float pm = a0 ? p0 : p_old;
        float s1 = a0 ? s1a : s1r;
        float m1 = s1 + b2v;
        float p1 = m1 * m1;
        float r1v = fminf(__fdividef(p1, pm + 1e-12f), 1.0f);
        bool a1 = us[t0 + 1] < r1v;
        p_old = a1 ? p1 : pm;

        // apply step t0
        if (a0) { zP = v0; cP = c0; xr += dx0; }
        if (t0 >= BURN) out[(t0 - BURN) * DIMX + tid] = xr;
        // apply step t1 (packed Kahan add of d1)
        if (a1) {
            ull e;  SUB2(e, d1, cP);
            ull zn; ADD2(zn, zP, e);
            ull u;  SUB2(u, zn, zP);
            SUB2(cP, u, e);
            zP = zn;
            xr += dx1;
        }
        if (t0 + 1 >= BURN) out[(t0 + 1 - BURN) * DIMX + tid] = xr;

        d0 = nd0; d1 = nd1; dx0 = ndx0; dx1 = ndx1;
    }
}

// ---------------- launch ----------------------------------------------------
extern "C" void kernel_launch(void* const* d_in, const int* in_sizes, int n_in,
                              void* d_out, int out_size) {
    const float* x0 = (const float*)d_in[0];
    const float* W1 = (const float*)d_in[1];
    const float* b1 = (const float*)d_in[2];
    const float* W2 = (const float*)d_in[3];
    const float* b2 = (const float*)d_in[4];
    float* out = (float*)d_out;

    noise_kernel<<<NSTEP, 256>>>();
    dz_gemm<<<dim3(HID / 256, NSTEP / GT), 256>>>(W1);
    z0_kernel<<<HID / 256, 256>>>(x0, W1, b1);
    chain_kernel<<<1, 512>>>(x0, W2, b2, out);
}